// round 3
// baseline (speedup 1.0000x reference)
#include <cuda_runtime.h>

// ---------------------------------------------------------------------------
// Popcnt_14731737825611 : 3-layer sparse-gather MLP, transposed-activation form.
//
// All activations kept as [O, B] (B=256 contiguous) so that a popcnt-layer
// gather  h[o,b] = sig( sum_p sw[o,p] * in[sel[o,p], b] - bias[o] )
// reads contiguous 1KB rows per (o,p) with a warp-uniform index.
// LayerNorm of the *input* of layers 2/3 is folded algebraically:
//   sum_p sw*( (v-mu_b)*r_b*g[i] + be[i] )
//     = r_b * ( A - mu_b*C1_o ) + C2_o,   A = sum sw*g[i]*v  (1 FMA/elem)
// with C1_o = sum sw*g[sel], C2_o = sum sw*be[sel] precomputed per output.
// ---------------------------------------------------------------------------

namespace {
constexpr int B    = 256;
constexpr int IN1  = 3200;
constexpr int O1   = 8192;
constexpr int O3   = 4096;
constexpr int P    = 128;
constexpr int NPART = 64;
}

// Scratch (static device allocations; no runtime allocs).
__device__ float g_xT [IN1 * B];
__device__ float g_h1 [O1  * B];
__device__ float g_h2 [O1  * B];
__device__ float g_h3 [O3  * B];
__device__ float g_sw1[O1 * P];
__device__ float g_sw2[O1 * P];
__device__ float g_sw3[O3 * P];
__device__ float g_C1b[O1];   // layer-2 input-LN constants
__device__ float g_C2b[O1];
__device__ float g_C1c[O3];   // layer-3 input-LN constants
__device__ float g_C2c[O3];
__device__ float g_ps[NPART * B];
__device__ float g_pq[NPART * B];
__device__ float g_mu[2][B];
__device__ float g_rs[2][B];

__device__ __forceinline__ float sigmoidf_fast(float x) {
    return 1.0f / (1.0f + __expf(-x));
}

// --- transpose x[B, IN1] -> g_xT[IN1, B] -----------------------------------
__global__ void k_transpose(const float* __restrict__ x) {
    __shared__ float t[32][33];
    const int i0 = blockIdx.x * 32;     // over IN1 (3200 = 100*32)
    const int b0 = blockIdx.y * 32;     // over B   (256 = 8*32)
    const int tx = threadIdx.x, ty = threadIdx.y;
#pragma unroll
    for (int j = 0; j < 32; j += 8)
        t[ty + j][tx] = x[(b0 + ty + j) * IN1 + (i0 + tx)];
    __syncthreads();
#pragma unroll
    for (int j = 0; j < 32; j += 8)
        g_xT[(i0 + ty + j) * B + (b0 + tx)] = t[tx][ty + j];
}

// --- weight prep -----------------------------------------------------------
__global__ void k_prep1(const float* __restrict__ w) {
    int i = blockIdx.x * 256 + threadIdx.x;
    g_sw1[i] = sigmoidf_fast(w[i]);
}

template <int L>   // L = 2 or 3 : also builds C1/C2 for the folded input-LN
__global__ void k_prep(const int* __restrict__ sel, const float* __restrict__ w,
                       const float* __restrict__ gamma, const float* __restrict__ beta) {
    float* sw = (L == 2) ? g_sw2 : g_sw3;
    float* C1 = (L == 2) ? g_C1b : g_C1c;
    float* C2 = (L == 2) ? g_C2b : g_C2c;
    const int o = blockIdx.x, p = threadIdx.x;
    const int idx = sel[o * P + p];
    const float s  = sigmoidf_fast(w[o * P + p]);
    const float swp = s * gamma[idx];
    const float c2  = s * beta[idx];
    sw[o * P + p] = swp;
    __shared__ float s1[P], s2[P];
    s1[p] = swp; s2[p] = c2;
    __syncthreads();
    for (int st = P / 2; st > 0; st >>= 1) {
        if (p < st) { s1[p] += s1[p + st]; s2[p] += s2[p + st]; }
        __syncthreads();
    }
    if (p == 0) { C1[o] = s1[0]; C2[o] = s2[0]; }
}

// --- popcnt layer: block = 256 threads = 4 outputs x 64 b-groups(4 b each) --
template <int L>
__global__ void __launch_bounds__(256) k_pop(const int* __restrict__ sel,
                                             const float* __restrict__ bias) {
    const float* inT  = (L == 1) ? g_xT  : (L == 2) ? g_h1  : g_h2;
    const float* sw   = (L == 1) ? g_sw1 : (L == 2) ? g_sw2 : g_sw3;
    float*       outT = (L == 1) ? g_h1  : (L == 2) ? g_h2  : g_h3;

    const int tid = threadIdx.x;
    const int og  = tid >> 6;            // 0..3 : output subgroup
    const int b0  = (tid & 63) * 4;      // 4 consecutive batch elements
    const int o   = blockIdx.x * 4 + og;

    float4 mu4 = make_float4(0.f, 0.f, 0.f, 0.f);
    float4 rs4 = make_float4(1.f, 1.f, 1.f, 1.f);
    float  c1 = 0.f, c2 = 0.f;
    if (L > 1) {
        mu4 = *reinterpret_cast<const float4*>(&g_mu[L - 2][b0]);
        rs4 = *reinterpret_cast<const float4*>(&g_rs[L - 2][b0]);
        c1  = ((L == 2) ? g_C1b : g_C1c)[o];
        c2  = ((L == 2) ? g_C2b : g_C2c)[o];
    }

    const int*   sp = sel + o * P;
    const float* wp = sw  + o * P;
    float a0 = 0.f, a1 = 0.f, a2 = 0.f, a3 = 0.f;
#pragma unroll 4
    for (int p = 0; p < P; ++p) {
        const int   idx = __ldg(sp + p);
        const float wv  = __ldg(wp + p);
        const float4 v  = *reinterpret_cast<const float4*>(inT + idx * B + b0);
        a0 = fmaf(wv, v.x, a0);
        a1 = fmaf(wv, v.y, a1);
        a2 = fmaf(wv, v.z, a2);
        a3 = fmaf(wv, v.w, a3);
    }

    const float bo = bias[o];
    float p0, p1, p2, p3;
    if (L > 1) {
        p0 = fmaf(rs4.x, a0 - mu4.x * c1, c2) - bo;
        p1 = fmaf(rs4.y, a1 - mu4.y * c1, c2) - bo;
        p2 = fmaf(rs4.z, a2 - mu4.z * c1, c2) - bo;
        p3 = fmaf(rs4.w, a3 - mu4.w * c1, c2) - bo;
    } else {
        p0 = a0 - bo; p1 = a1 - bo; p2 = a2 - bo; p3 = a3 - bo;
    }
    float4 r;
    r.x = sigmoidf_fast(p0);
    r.y = sigmoidf_fast(p1);
    r.z = sigmoidf_fast(p2);
    r.w = sigmoidf_fast(p3);
    *reinterpret_cast<float4*>(outT + o * B + b0) = r;
}

// --- layer-norm statistics over the O dimension (per batch column b) -------
template <int L>   // L=1 : stats of g_h1, L=2 : stats of g_h2
__global__ void k_ln_part() {
    const float* h = (L == 1) ? g_h1 : g_h2;
    const int tid = threadIdx.x;
    const int rows = O1 / NPART;               // 128
    const int r0 = blockIdx.x * rows;
    float s = 0.f, q = 0.f;
    for (int r = r0; r < r0 + rows; ++r) {
        const float v = h[r * B + tid];
        s += v;
        q = fmaf(v, v, q);
    }
    g_ps[blockIdx.x * B + tid] = s;
    g_pq[blockIdx.x * B + tid] = q;
}

template <int L>
__global__ void k_ln_fin() {
    const int tid = threadIdx.x;
    float s = 0.f, q = 0.f;
    for (int i = 0; i < NPART; ++i) { s += g_ps[i * B + tid]; q += g_pq[i * B + tid]; }
    const float m   = s * (1.0f / O1);
    const float var = q * (1.0f / O1) - m * m;
    g_mu[L - 1][tid] = m;
    g_rs[L - 1][tid] = rsqrtf(var + 1e-12f);
}

// --- final: group-sum of 16 + bias, out[b, g] ------------------------------
__global__ void k_final(float* __restrict__ out) {
    const int gg = blockIdx.x;     // 0..255 group
    const int tid = threadIdx.x;   // b
    float acc = 0.f;
#pragma unroll
    for (int j = 0; j < 16; ++j)
        acc += g_h3[(gg * 16 + j) * B + tid];
    out[tid * 256 + gg] = acc - 8.0f;
}

// ---------------------------------------------------------------------------
extern "C" void kernel_launch(void* const* d_in, const int* in_sizes, int n_in,
                              void* d_out, int out_size) {
    (void)in_sizes; (void)n_in; (void)out_size;
    const float* x    = (const float*)d_in[0];
    const int*   sel1 = (const int*)  d_in[1];
    const float* w1   = (const float*)d_in[2];
    const float* b1   = (const float*)d_in[3];
    const float* g1   = (const float*)d_in[4];
    const float* be1  = (const float*)d_in[5];
    const int*   sel2 = (const int*)  d_in[6];
    const float* w2   = (const float*)d_in[7];
    const float* b2   = (const float*)d_in[8];
    const float* g2   = (const float*)d_in[9];
    const float* be2  = (const float*)d_in[10];
    const int*   sel3 = (const int*)  d_in[11];
    const float* w3   = (const float*)d_in[12];
    const float* b3   = (const float*)d_in[13];
    float* out = (float*)d_out;

    k_transpose<<<dim3(IN1 / 32, B / 32), dim3(32, 8)>>>(x);
    k_prep1<<<O1 * P / 256, 256>>>(w1);
    k_prep<2><<<O1, P>>>(sel2, w2, g1, be1);
    k_prep<3><<<O3, P>>>(sel3, w3, g2, be2);

    k_pop<1><<<O1 / 4, 256>>>(sel1, b1);
    k_ln_part<1><<<NPART, 256>>>();
    k_ln_fin<1><<<1, 256>>>();

    k_pop<2><<<O1 / 4, 256>>>(sel2, b2);
    k_ln_part<2><<<NPART, 256>>>();
    k_ln_fin<2><<<1, 256>>>();

    k_pop<3><<<O3 / 4, 256>>>(sel3, b3);
    k_final<<<256, 256>>>(out);
}

// round 4
// speedup vs baseline: 1.4730x; 1.4730x over previous
#include <cuda_runtime.h>
#include <cuda_fp16.h>

// ---------------------------------------------------------------------------
// Popcnt_14731737825611 : 3-layer sparse-gather MLP.
// R3: fp16 activation storage (halves L2 gather traffic), interleaved
// (sel, sigmoid(w)*gamma) pair tables (one uniform LDG.64 per p), warp-per-
// output prep kernels with shuffle reductions, 8 batch elements per thread.
// LayerNorm of layer-2/3 inputs folded algebraically via C1/C2 constants.
// ---------------------------------------------------------------------------

namespace {
constexpr int B    = 256;
constexpr int IN1  = 3200;
constexpr int O1   = 8192;
constexpr int O3   = 4096;
constexpr int P    = 128;
constexpr int NPART = 64;
}

// Static device scratch (no runtime allocs).
__device__ __half g_xT [IN1 * B];
__device__ __half g_h1 [O1  * B];
__device__ __half g_h2 [O1  * B];
__device__ __half g_h3 [O3  * B];
__device__ uint2  g_pk1[O1 * P];   // (sel, sig(w)) interleaved
__device__ uint2  g_pk2[O1 * P];   // (sel, sig(w)*gamma1)
__device__ uint2  g_pk3[O3 * P];   // (sel, sig(w)*gamma2)
__device__ float  g_C1b[O1];
__device__ float  g_C2b[O1];
__device__ float  g_C1c[O3];
__device__ float  g_C2c[O3];
__device__ float  g_ps[NPART * B];
__device__ float  g_pq[NPART * B];
__device__ float  g_mu[2][B];
__device__ float  g_rs[2][B];

__device__ __forceinline__ float sigmoidf_fast(float x) {
    return 1.0f / (1.0f + __expf(-x));
}

// --- transpose x[B, IN1] -> g_xT[IN1, B] (fp16) ----------------------------
__global__ void k_transpose(const float* __restrict__ x) {
    __shared__ float t[32][33];
    const int i0 = blockIdx.x * 32;     // over IN1 (3200 = 100*32)
    const int b0 = blockIdx.y * 32;     // over B   (256 = 8*32)
    const int tx = threadIdx.x, ty = threadIdx.y;
#pragma unroll
    for (int j = 0; j < 32; j += 8)
        t[ty + j][tx] = x[(b0 + ty + j) * IN1 + (i0 + tx)];
    __syncthreads();
#pragma unroll
    for (int j = 0; j < 32; j += 8)
        g_xT[(i0 + ty + j) * B + (b0 + tx)] = __float2half_rn(t[tx][ty + j]);
}

// --- layer-1 pair prep: pair = (sel, sigmoid(w)) ---------------------------
__global__ void k_prep1(const int* __restrict__ sel, const float* __restrict__ w) {
    const int i = blockIdx.x * blockDim.x + threadIdx.x;   // over (O1*P)/4
    const int4   s  = reinterpret_cast<const int4*>(sel)[i];
    const float4 wv = reinterpret_cast<const float4*>(w)[i];
    uint4 a, b;
    a.x = (unsigned)s.x; a.y = __float_as_uint(sigmoidf_fast(wv.x));
    a.z = (unsigned)s.y; a.w = __float_as_uint(sigmoidf_fast(wv.y));
    b.x = (unsigned)s.z; b.y = __float_as_uint(sigmoidf_fast(wv.z));
    b.z = (unsigned)s.w; b.w = __float_as_uint(sigmoidf_fast(wv.w));
    reinterpret_cast<uint4*>(g_pk1)[2 * i]     = a;
    reinterpret_cast<uint4*>(g_pk1)[2 * i + 1] = b;
}

// --- layer-2/3 prep: pair = (sel, sig(w)*gamma[sel]); C1/C2 via warp reduce
template <int L>
__global__ void k_prep(const int* __restrict__ sel, const float* __restrict__ w,
                       const float* __restrict__ gamma, const float* __restrict__ beta) {
    uint2* pk = (L == 2) ? g_pk2 : g_pk3;
    float* C1 = (L == 2) ? g_C1b : g_C1c;
    float* C2 = (L == 2) ? g_C2b : g_C2c;
    const int o    = blockIdx.x * 8 + (threadIdx.x >> 5);
    const int lane = threadIdx.x & 31;
    const int4   s  = reinterpret_cast<const int4*>(sel + o * P)[lane];
    const float4 wv = reinterpret_cast<const float4*>(w   + o * P)[lane];
    float sg[4] = { sigmoidf_fast(wv.x), sigmoidf_fast(wv.y),
                    sigmoidf_fast(wv.z), sigmoidf_fast(wv.w) };
    const int  idx[4] = { s.x, s.y, s.z, s.w };
    float swg[4], c1 = 0.f, c2 = 0.f;
#pragma unroll
    for (int j = 0; j < 4; ++j) {
        swg[j] = sg[j] * __ldg(gamma + idx[j]);
        c1 += swg[j];
        c2 = fmaf(sg[j], __ldg(beta + idx[j]), c2);
    }
    uint4 a, b;
    a.x = (unsigned)idx[0]; a.y = __float_as_uint(swg[0]);
    a.z = (unsigned)idx[1]; a.w = __float_as_uint(swg[1]);
    b.x = (unsigned)idx[2]; b.y = __float_as_uint(swg[2]);
    b.z = (unsigned)idx[3]; b.w = __float_as_uint(swg[3]);
    reinterpret_cast<uint4*>(pk)[o * 64 + lane * 2]     = a;
    reinterpret_cast<uint4*>(pk)[o * 64 + lane * 2 + 1] = b;
#pragma unroll
    for (int st = 16; st > 0; st >>= 1) {
        c1 += __shfl_xor_sync(0xffffffffu, c1, st);
        c2 += __shfl_xor_sync(0xffffffffu, c2, st);
    }
    if (lane == 0) { C1[o] = c1; C2[o] = c2; }
}

// --- popcnt layer: 1 warp = 1 output, lane covers 8 batch elements ---------
template <int L>
__global__ void __launch_bounds__(256) k_pop(const float* __restrict__ bias) {
    const __half* inT  = (L == 1) ? g_xT  : (L == 2) ? g_h1  : g_h2;
    const uint2*  pk   = (L == 1) ? g_pk1 : (L == 2) ? g_pk2 : g_pk3;
    __half*       outT = (L == 1) ? g_h1  : (L == 2) ? g_h2  : g_h3;

    const int lane = threadIdx.x & 31;
    const int o    = blockIdx.x * 8 + (threadIdx.x >> 5);
    const int b0   = lane * 8;                 // 8 halves = one 16B load

    float acc[8];
#pragma unroll
    for (int j = 0; j < 8; ++j) acc[j] = 0.f;

    const uint2* pp = pk + o * P;
#pragma unroll 16
    for (int p = 0; p < P; ++p) {
        const uint2 pr = __ldg(pp + p);            // warp-uniform (idx, w)
        const float wv = __uint_as_float(pr.y);
        const uint4 v  = *reinterpret_cast<const uint4*>(inT + pr.x * B + b0);
        const float2 f0 = __half22float2(*reinterpret_cast<const __half2*>(&v.x));
        const float2 f1 = __half22float2(*reinterpret_cast<const __half2*>(&v.y));
        const float2 f2 = __half22float2(*reinterpret_cast<const __half2*>(&v.z));
        const float2 f3 = __half22float2(*reinterpret_cast<const __half2*>(&v.w));
        acc[0] = fmaf(wv, f0.x, acc[0]);
        acc[1] = fmaf(wv, f0.y, acc[1]);
        acc[2] = fmaf(wv, f1.x, acc[2]);
        acc[3] = fmaf(wv, f1.y, acc[3]);
        acc[4] = fmaf(wv, f2.x, acc[4]);
        acc[5] = fmaf(wv, f2.y, acc[5]);
        acc[6] = fmaf(wv, f3.x, acc[6]);
        acc[7] = fmaf(wv, f3.y, acc[7]);
    }

    const float bo = bias[o];
    float pre[8];
    if (L > 1) {
        const float c1 = ((L == 2) ? g_C1b : g_C1c)[o];
        const float c2 = ((L == 2) ? g_C2b : g_C2c)[o];
        const float4 m0 = *reinterpret_cast<const float4*>(&g_mu[L - 2][b0]);
        const float4 m1 = *reinterpret_cast<const float4*>(&g_mu[L - 2][b0 + 4]);
        const float4 r0 = *reinterpret_cast<const float4*>(&g_rs[L - 2][b0]);
        const float4 r1 = *reinterpret_cast<const float4*>(&g_rs[L - 2][b0 + 4]);
        const float mu[8] = { m0.x, m0.y, m0.z, m0.w, m1.x, m1.y, m1.z, m1.w };
        const float rs[8] = { r0.x, r0.y, r0.z, r0.w, r1.x, r1.y, r1.z, r1.w };
#pragma unroll
        for (int j = 0; j < 8; ++j)
            pre[j] = fmaf(rs[j], acc[j] - mu[j] * c1, c2) - bo;
    } else {
#pragma unroll
        for (int j = 0; j < 8; ++j) pre[j] = acc[j] - bo;
    }

    uint4 outv;
    __half2 h01 = __floats2half2_rn(sigmoidf_fast(pre[0]), sigmoidf_fast(pre[1]));
    __half2 h23 = __floats2half2_rn(sigmoidf_fast(pre[2]), sigmoidf_fast(pre[3]));
    __half2 h45 = __floats2half2_rn(sigmoidf_fast(pre[4]), sigmoidf_fast(pre[5]));
    __half2 h67 = __floats2half2_rn(sigmoidf_fast(pre[6]), sigmoidf_fast(pre[7]));
    outv.x = *reinterpret_cast<unsigned*>(&h01);
    outv.y = *reinterpret_cast<unsigned*>(&h23);
    outv.z = *reinterpret_cast<unsigned*>(&h45);
    outv.w = *reinterpret_cast<unsigned*>(&h67);
    *reinterpret_cast<uint4*>(outT + o * B + b0) = outv;
}

// --- layer-norm statistics over the O dimension (per batch column b) -------
template <int L>
__global__ void k_ln_part() {
    const __half* h = (L == 1) ? g_h1 : g_h2;
    const int tid = threadIdx.x;
    const int rows = O1 / NPART;               // 128
    const int r0 = blockIdx.x * rows;
    float s = 0.f, q = 0.f;
    for (int r = r0; r < r0 + rows; ++r) {
        const float v = __half2float(h[r * B + tid]);
        s += v;
        q = fmaf(v, v, q);
    }
    g_ps[blockIdx.x * B + tid] = s;
    g_pq[blockIdx.x * B + tid] = q;
}

template <int L>
__global__ void k_ln_fin() {
    const int tid = threadIdx.x;
    float s = 0.f, q = 0.f;
    for (int i = 0; i < NPART; ++i) { s += g_ps[i * B + tid]; q += g_pq[i * B + tid]; }
    const float m   = s * (1.0f / O1);
    const float var = q * (1.0f / O1) - m * m;
    g_mu[L - 1][tid] = m;
    g_rs[L - 1][tid] = rsqrtf(var + 1e-12f);
}

// --- final: group-sum of 16 + bias, out[b, g] ------------------------------
__global__ void k_final(float* __restrict__ out) {
    const int gg = blockIdx.x;     // 0..255 group
    const int tid = threadIdx.x;   // b
    float acc = 0.f;
#pragma unroll
    for (int j = 0; j < 16; ++j)
        acc += __half2float(g_h3[(gg * 16 + j) * B + tid]);
    out[tid * 256 + gg] = acc - 8.0f;
}

// ---------------------------------------------------------------------------
extern "C" void kernel_launch(void* const* d_in, const int* in_sizes, int n_in,
                              void* d_out, int out_size) {
    (void)in_sizes; (void)n_in; (void)out_size;
    const float* x    = (const float*)d_in[0];
    const int*   sel1 = (const int*)  d_in[1];
    const float* w1   = (const float*)d_in[2];
    const float* b1   = (const float*)d_in[3];
    const float* g1   = (const float*)d_in[4];
    const float* be1  = (const float*)d_in[5];
    const int*   sel2 = (const int*)  d_in[6];
    const float* w2   = (const float*)d_in[7];
    const float* b2   = (const float*)d_in[8];
    const float* g2   = (const float*)d_in[9];
    const float* be2  = (const float*)d_in[10];
    const int*   sel3 = (const int*)  d_in[11];
    const float* w3   = (const float*)d_in[12];
    const float* b3   = (const float*)d_in[13];
    float* out = (float*)d_out;

    k_transpose<<<dim3(IN1 / 32, B / 32), dim3(32, 8)>>>(x);
    k_prep1<<<(O1 * P / 4) / 256, 256>>>(sel1, w1);
    k_prep<2><<<O1 / 8, 256>>>(sel2, w2, g1, be1);
    k_prep<3><<<O3 / 8, 256>>>(sel3, w3, g2, be2);

    k_pop<1><<<O1 / 8, 256>>>(b1);
    k_ln_part<1><<<NPART, 256>>>();
    k_ln_fin<1><<<1, 256>>>();

    k_pop<2><<<O1 / 8, 256>>>(b2);
    k_ln_part<2><<<NPART, 256>>>();
    k_ln_fin<2><<<1, 256>>>();

    k_pop<3><<<O3 / 8, 256>>>(b3);
    k_final<<<256, 256>>>(out);
}